// round 2
// baseline (speedup 1.0000x reference)
#include <cuda_runtime.h>

#define BB 512
#define TT 128
#define CC 384
#define HD 64
#define CB 32
#define NT 256
#define PADQ 65
#define PADS 129
#define ATT_SCALE 0.4082482904638631f  // 6^-0.5

// Dynamic smem layout (floats):
//  sQ: 128*65          = 8320
//  sK: 128*65          = 8320
//  sV: 128*65          = 8320
//  sS: 128*129         = 16512   (scratch: also holds sX 128*33 + sW 3*32*64)
//  rowInv: 128
// total = 41600 floats = 166400 bytes
#define SMEM_FLOATS 41600
#define SMEM_BYTES (SMEM_FLOATS * 4)

__global__ __launch_bounds__(NT, 1)
void head_fused_kernel(const float* __restrict__ x,
                       const float* __restrict__ Wq,
                       const float* __restrict__ Wk,
                       const float* __restrict__ Wv,
                       float* __restrict__ out) {
    extern __shared__ float sm[];
    float* sQ = sm;                        // [128][65]
    float* sK = sQ + TT * PADQ;
    float* sV = sK + TT * PADQ;
    float* sS = sV + TT * PADQ;            // [128][129], reused as sX/sW first
    float* sX = sS;                        // [128][33]
    float* sW = sS + TT * 33;              // [3][32][64]
    float* rowInv = sS + TT * PADS;        // [128]

    const int b   = blockIdx.x;
    const int tid = threadIdx.x;
    const int hh  = tid & 7;    // h-group: h = hh + 8*j
    const int ttf = tid >> 3;   // t-group: t = ttf + 32*i

    const float* xb = x + (size_t)b * TT * CC;

    // ---------------- Projections: Q,K,V = X * W{q,k,v} ----------------
    float aq[4][8], ak[4][8], av[4][8];
    #pragma unroll
    for (int i = 0; i < 4; i++)
        #pragma unroll
        for (int j = 0; j < 8; j++) { aq[i][j] = 0.f; ak[i][j] = 0.f; av[i][j] = 0.f; }

    for (int c0 = 0; c0 < CC; c0 += CB) {
        // load X tile [128][32] (1024 float4, 4 per thread)
        #pragma unroll
        for (int rep = 0; rep < 4; rep++) {
            int lin  = rep * NT + tid;      // float4 index
            int row  = lin >> 3;            // 8 float4 per row
            int col4 = (lin & 7) << 2;
            float4 xv = *reinterpret_cast<const float4*>(xb + row * CC + c0 + col4);
            float* d = sX + row * 33 + col4;
            d[0] = xv.x; d[1] = xv.y; d[2] = xv.z; d[3] = xv.w;
        }
        // load W tiles [32][64] x3 (512 float4 each, 2 per thread)
        #pragma unroll
        for (int rep = 0; rep < 2; rep++) {
            int lin  = rep * NT + tid;      // float4 index (512 total)
            int row  = lin >> 4;            // 16 float4 per row
            int col4 = (lin & 15) << 2;
            int goff = (c0 + row) * HD + col4;
            float4 wq4 = *reinterpret_cast<const float4*>(Wq + goff);
            float4 wk4 = *reinterpret_cast<const float4*>(Wk + goff);
            float4 wv4 = *reinterpret_cast<const float4*>(Wv + goff);
            int soff = row * HD + col4;
            float* dq = sW + soff;
            float* dk = sW + 2048 + soff;
            float* dv = sW + 4096 + soff;
            dq[0]=wq4.x; dq[1]=wq4.y; dq[2]=wq4.z; dq[3]=wq4.w;
            dk[0]=wk4.x; dk[1]=wk4.y; dk[2]=wk4.z; dk[3]=wk4.w;
            dv[0]=wv4.x; dv[1]=wv4.y; dv[2]=wv4.z; dv[3]=wv4.w;
        }
        __syncthreads();

        #pragma unroll 4
        for (int cc = 0; cc < CB; cc++) {
            float xv[4];
            #pragma unroll
            for (int i = 0; i < 4; i++) xv[i] = sX[(ttf + 32 * i) * 33 + cc];
            #pragma unroll
            for (int j = 0; j < 8; j++) {
                int hcol = cc * HD + hh + 8 * j;
                float wq = sW[hcol];
                float wk = sW[2048 + hcol];
                float wv = sW[4096 + hcol];
                #pragma unroll
                for (int i = 0; i < 4; i++) {
                    aq[i][j] = fmaf(xv[i], wq, aq[i][j]);
                    ak[i][j] = fmaf(xv[i], wk, ak[i][j]);
                    av[i][j] = fmaf(xv[i], wv, av[i][j]);
                }
            }
        }
        __syncthreads();
    }

    // store projections to smem
    #pragma unroll
    for (int i = 0; i < 4; i++) {
        int t = ttf + 32 * i;
        #pragma unroll
        for (int j = 0; j < 8; j++) {
            int h = hh + 8 * j;
            sQ[t * PADQ + h] = aq[i][j];
            sK[t * PADQ + h] = ak[i][j];
            sV[t * PADQ + h] = av[i][j];
        }
    }
    __syncthreads();

    // ---------------- Scores: S = scale * Q K^T ----------------
    {
        const int ss = tid & 7;  // s = ss + 8*j, j in [0,16)
        float sc[4][16];
        #pragma unroll
        for (int i = 0; i < 4; i++)
            #pragma unroll
            for (int j = 0; j < 16; j++) sc[i][j] = 0.f;

        #pragma unroll 4
        for (int h = 0; h < HD; h++) {
            float qv[4];
            #pragma unroll
            for (int i = 0; i < 4; i++) qv[i] = sQ[(ttf + 32 * i) * PADQ + h];
            #pragma unroll
            for (int j = 0; j < 16; j++) {
                float kv = sK[(ss + 8 * j) * PADQ + h];
                #pragma unroll
                for (int i = 0; i < 4; i++)
                    sc[i][j] = fmaf(qv[i], kv, sc[i][j]);
            }
        }
        #pragma unroll
        for (int i = 0; i < 4; i++) {
            int t = ttf + 32 * i;
            #pragma unroll
            for (int j = 0; j < 16; j++)
                sS[t * PADS + ss + 8 * j] = sc[i][j] * ATT_SCALE;
        }
    }
    __syncthreads();

    // ---------------- Causal softmax (one thread per row) ----------------
    if (tid < TT) {
        const int r = tid;
        float* row = sS + r * PADS;
        float mx = row[0];
        for (int s = 1; s <= r; s++) mx = fmaxf(mx, row[s]);
        float sum = 0.f;
        for (int s = 0; s <= r; s++) {
            float p = __expf(row[s] - mx);
            row[s] = p;
            sum += p;
        }
        for (int s = r + 1; s < TT; s++) row[s] = 0.f;
        rowInv[r] = 1.0f / sum;
    }
    __syncthreads();

    // ---------------- Output: O = (P V) / rowsum ----------------
    {
        float ao[4][8];
        #pragma unroll
        for (int i = 0; i < 4; i++)
            #pragma unroll
            for (int j = 0; j < 8; j++) ao[i][j] = 0.f;

        #pragma unroll 4
        for (int s = 0; s < TT; s++) {
            float pv[4];
            #pragma unroll
            for (int i = 0; i < 4; i++) pv[i] = sS[(ttf + 32 * i) * PADS + s];
            #pragma unroll
            for (int j = 0; j < 8; j++) {
                float vv = sV[s * PADQ + hh + 8 * j];
                #pragma unroll
                for (int i = 0; i < 4; i++)
                    ao[i][j] = fmaf(pv[i], vv, ao[i][j]);
            }
        }

        float* ob = out + (size_t)b * TT * HD;
        #pragma unroll
        for (int i = 0; i < 4; i++) {
            int t = ttf + 32 * i;
            float inv = rowInv[t];
            #pragma unroll
            for (int j = 0; j < 8; j++)
                ob[t * HD + hh + 8 * j] = ao[i][j] * inv;
        }
    }
}

extern "C" void kernel_launch(void* const* d_in, const int* in_sizes, int n_in,
                              void* d_out, int out_size) {
    const float* x  = (const float*)d_in[0];
    const float* Wq = (const float*)d_in[1];
    const float* Wk = (const float*)d_in[2];
    const float* Wv = (const float*)d_in[3];
    float* out = (float*)d_out;

    cudaFuncSetAttribute(head_fused_kernel,
                         cudaFuncAttributeMaxDynamicSharedMemorySize, SMEM_BYTES);
    head_fused_kernel<<<BB, NT, SMEM_BYTES>>>(x, Wq, Wk, Wv, out);
}

// round 7
// speedup vs baseline: 2.6389x; 2.6389x over previous
#include <cuda_runtime.h>
#include <cstdint>

#define BB 512
#define TT 128
#define CC 384
#define HD 64
#define NT 256
#define ATT_SCALE 0.4082482904638631f  // 6^-0.5

// ---- smem layout (floats). Region0 aliased: phase1 operands vs score matrix P.
//  sXhi [128][36] @0      (4608)
//  sXlo [128][36] @4608   (4608)
//  sWhi [32][200] @9216   (6400)
//  sWlo [32][200] @15616  (6400)   end 22016
//  sS   [128][132] @0     (16896)  (aliases the above, used after barrier)
//  sQ   [128][68] @22016  (8704)
//  sK   [128][68] @30720  (8704)
//  sV   [128][72] @39424  (9216)   end 48640 floats = 194560 bytes
#define OXH 0
#define OXL 4608
#define OWH 9216
#define OWL 15616
#define OS  0
#define OQ  22016
#define OK  30720
#define OV  39424
#define SMEM_FLOATS 48640
#define SMEM_BYTES (SMEM_FLOATS * 4)

__device__ __forceinline__ uint32_t f2tf32(float x) {
    uint32_t r;
    asm("cvt.rna.tf32.f32 %0, %1;" : "=r"(r) : "f"(x));
    return r;
}
__device__ __forceinline__ void split_tf32(float x, uint32_t& hi, uint32_t& lo) {
    hi = f2tf32(x);
    lo = f2tf32(x - __uint_as_float(hi));
}
__device__ __forceinline__ void mma_tf32(float* d, const uint32_t* a, uint32_t b0, uint32_t b1) {
    asm volatile(
        "mma.sync.aligned.m16n8k8.row.col.f32.tf32.tf32.f32 "
        "{%0,%1,%2,%3}, {%4,%5,%6,%7}, {%8,%9}, {%0,%1,%2,%3};"
        : "+f"(d[0]), "+f"(d[1]), "+f"(d[2]), "+f"(d[3])
        : "r"(a[0]), "r"(a[1]), "r"(a[2]), "r"(a[3]), "r"(b0), "r"(b1));
}

__global__ __launch_bounds__(NT, 1)
void head_mma_kernel(const float* __restrict__ x,
                     const float* __restrict__ Wq,
                     const float* __restrict__ Wk,
                     const float* __restrict__ Wv,
                     float* __restrict__ out) {
    extern __shared__ float sm[];
    const int tid  = threadIdx.x;
    const int lane = tid & 31;
    const int wid  = tid >> 5;
    const int g    = lane >> 2;   // 0..7
    const int q4   = lane & 3;    // 0..3
    const int b    = blockIdx.x;
    const float* xb = x + (size_t)b * TT * CC;
    const float* Ws[3] = {Wq, Wk, Wv};

    // ================= Phase 1: QKV projection =================
    // warp tile: wm = wid&3 -> 32 rows; wn = wid>>2 -> 96 cols of 192
    const int wm = wid & 3;
    const int wn = wid >> 2;

    float accp[2][12][4];
    #pragma unroll
    for (int mi = 0; mi < 2; mi++)
        #pragma unroll
        for (int ni = 0; ni < 12; ni++)
            #pragma unroll
            for (int j = 0; j < 4; j++) accp[mi][ni][j] = 0.f;

    for (int ch = 0; ch < 12; ch++) {
        if (ch) __syncthreads();
        // X chunk [128][32] -> hi/lo (1024 float4, 4/thread)
        #pragma unroll
        for (int rep = 0; rep < 4; rep++) {
            int lin = rep * NT + tid;
            int row = lin >> 3;
            int c4  = (lin & 7) << 2;
            float4 v = *reinterpret_cast<const float4*>(xb + row * CC + ch * 32 + c4);
            float4 h, l;
            uint32_t uh, ul;
            split_tf32(v.x, uh, ul); h.x = __uint_as_float(uh); l.x = __uint_as_float(ul);
            split_tf32(v.y, uh, ul); h.y = __uint_as_float(uh); l.y = __uint_as_float(ul);
            split_tf32(v.z, uh, ul); h.z = __uint_as_float(uh); l.z = __uint_as_float(ul);
            split_tf32(v.w, uh, ul); h.w = __uint_as_float(uh); l.w = __uint_as_float(ul);
            int off = row * 36 + c4;
            *reinterpret_cast<float4*>(sm + OXH + off) = h;
            *reinterpret_cast<float4*>(sm + OXL + off) = l;
        }
        // W chunk [32][192] -> hi/lo (1536 float4, 6/thread)
        #pragma unroll
        for (int rep = 0; rep < 6; rep++) {
            int lin  = rep * NT + tid;
            int wsel = lin >> 9;
            int rem  = lin & 511;
            int row  = rem >> 4;
            int c4   = (rem & 15) << 2;
            float4 v = *reinterpret_cast<const float4*>(Ws[wsel] + (ch * 32 + row) * HD + c4);
            float4 h, l;
            uint32_t uh, ul;
            split_tf32(v.x, uh, ul); h.x = __uint_as_float(uh); l.x = __uint_as_float(ul);
            split_tf32(v.y, uh, ul); h.y = __uint_as_float(uh); l.y = __uint_as_float(ul);
            split_tf32(v.z, uh, ul); h.z = __uint_as_float(uh); l.z = __uint_as_float(ul);
            split_tf32(v.w, uh, ul); h.w = __uint_as_float(uh); l.w = __uint_as_float(ul);
            int off = row * 200 + wsel * HD + c4;
            *reinterpret_cast<float4*>(sm + OWH + off) = h;
            *reinterpret_cast<float4*>(sm + OWL + off) = l;
        }
        __syncthreads();

        #pragma unroll
        for (int k8 = 0; k8 < 4; k8++) {
            int kk = k8 * 8 + q4;
            uint32_t ahi[2][4], alo[2][4];
            #pragma unroll
            for (int mi = 0; mi < 2; mi++) {
                int r = wm * 32 + mi * 16 + g;
                ahi[mi][0] = __float_as_uint(sm[OXH + r * 36 + kk]);
                ahi[mi][1] = __float_as_uint(sm[OXH + (r + 8) * 36 + kk]);
                ahi[mi][2] = __float_as_uint(sm[OXH + r * 36 + kk + 4]);
                ahi[mi][3] = __float_as_uint(sm[OXH + (r + 8) * 36 + kk + 4]);
                alo[mi][0] = __float_as_uint(sm[OXL + r * 36 + kk]);
                alo[mi][1] = __float_as_uint(sm[OXL + (r + 8) * 36 + kk]);
                alo[mi][2] = __float_as_uint(sm[OXL + r * 36 + kk + 4]);
                alo[mi][3] = __float_as_uint(sm[OXL + (r + 8) * 36 + kk + 4]);
            }
            #pragma unroll
            for (int ni = 0; ni < 12; ni++) {
                int nb   = wn * 96 + ni * 8;
                int boff = (k8 * 8 + q4) * 200 + nb + g;
                uint32_t bh0 = __float_as_uint(sm[OWH + boff]);
                uint32_t bh1 = __float_as_uint(sm[OWH + boff + 800]);
                mma_tf32(accp[0][ni], ahi[0], bh0, bh1);
                mma_tf32(accp[1][ni], ahi[1], bh0, bh1);
                if (nb < 128) {  // Q,K columns: 3xTF32 compensation
                    uint32_t bl0 = __float_as_uint(sm[OWL + boff]);
                    uint32_t bl1 = __float_as_uint(sm[OWL + boff + 800]);
                    mma_tf32(accp[0][ni], ahi[0], bl0, bl1);
                    mma_tf32(accp[1][ni], ahi[1], bl0, bl1);
                    mma_tf32(accp[0][ni], alo[0], bh0, bh1);
                    mma_tf32(accp[1][ni], alo[1], bh0, bh1);
                }
            }
        }
    }

    // store Q,K (fp32) and V (tf32-rounded) to smem
    #pragma unroll
    for (int mi = 0; mi < 2; mi++) {
        #pragma unroll
        for (int ni = 0; ni < 12; ni++) {
            int nc = wn * 96 + ni * 8 + 2 * q4;
            #pragma unroll
            for (int half = 0; half < 2; half++) {
                int r = wm * 32 + mi * 16 + g + half * 8;
                float v0 = accp[mi][ni][half * 2];
                float v1 = accp[mi][ni][half * 2 + 1];
                if (nc < 64) {
                    *reinterpret_cast<float2*>(sm + OQ + r * 68 + nc) = make_float2(v0, v1);
                } else if (nc < 128) {
                    *reinterpret_cast<float2*>(sm + OK + r * 68 + nc - 64) = make_float2(v0, v1);
                } else {
                    *reinterpret_cast<float2*>(sm + OV + r * 72 + nc - 128) =
                        make_float2(__uint_as_float(f2tf32(v0)), __uint_as_float(f2tf32(v1)));
                }
            }
        }
    }
    __syncthreads();  // QKV visible; phase-1 operand region now reusable as sS

    // ================= Phase 2: S = Q K^T (3xTF32), rows m0..m0+15 =================
    const int m0 = wid * 16;
    float acc2[16][4];
    #pragma unroll
    for (int ni = 0; ni < 16; ni++)
        #pragma unroll
        for (int j = 0; j < 4; j++) acc2[ni][j] = 0.f;

    #pragma unroll
    for (int k8 = 0; k8 < 8; k8++) {
        int kk = k8 * 8 + q4;
        uint32_t ah[4], al[4];
        split_tf32(sm[OQ + (m0 + g) * 68 + kk],         ah[0], al[0]);
        split_tf32(sm[OQ + (m0 + g + 8) * 68 + kk],     ah[1], al[1]);
        split_tf32(sm[OQ + (m0 + g) * 68 + kk + 4],     ah[2], al[2]);
        split_tf32(sm[OQ + (m0 + g + 8) * 68 + kk + 4], ah[3], al[3]);
        #pragma unroll
        for (int ni = 0; ni < 16; ni++) {
            int koff = (ni * 8 + g) * 68 + kk;
            uint32_t bh0, bl0, bh1, bl1;
            split_tf32(sm[OK + koff],     bh0, bl0);
            split_tf32(sm[OK + koff + 4], bh1, bl1);
            mma_tf32(acc2[ni], ah, bh0, bh1);
            mma_tf32(acc2[ni], ah, bl0, bl1);
            mma_tf32(acc2[ni], al, bh0, bh1);
        }
    }

    // ================= causal softmax in registers (4-lane shfl reduce) =======
    {
        int r0 = m0 + g, r1 = r0 + 8;
        float mx0 = -1e30f, mx1 = -1e30f;
        #pragma unroll
        for (int ni = 0; ni < 16; ni++)
            #pragma unroll
            for (int j = 0; j < 2; j++) {
                int c = ni * 8 + 2 * q4 + j;
                float s0 = acc2[ni][j] * ATT_SCALE;
                float s1 = acc2[ni][2 + j] * ATT_SCALE;
                acc2[ni][j]     = (c <= r0) ? s0 : -1e30f;
                acc2[ni][2 + j] = (c <= r1) ? s1 : -1e30f;
                mx0 = fmaxf(mx0, acc2[ni][j]);
                mx1 = fmaxf(mx1, acc2[ni][2 + j]);
            }
        mx0 = fmaxf(mx0, __shfl_xor_sync(0xffffffffu, mx0, 1));
        mx0 = fmaxf(mx0, __shfl_xor_sync(0xffffffffu, mx0, 2));
        mx1 = fmaxf(mx1, __shfl_xor_sync(0xffffffffu, mx1, 1));
        mx1 = fmaxf(mx1, __shfl_xor_sync(0xffffffffu, mx1, 2));
        float sum0 = 0.f, sum1 = 0.f;
        #pragma unroll
        for (int ni = 0; ni < 16; ni++)
            #pragma unroll
            for (int j = 0; j < 2; j++) {
                float e0 = __expf(acc2[ni][j] - mx0);
                float e1 = __expf(acc2[ni][2 + j] - mx1);
                acc2[ni][j] = e0; acc2[ni][2 + j] = e1;
                sum0 += e0; sum1 += e1;
            }
        sum0 += __shfl_xor_sync(0xffffffffu, sum0, 1);
        sum0 += __shfl_xor_sync(0xffffffffu, sum0, 2);
        sum1 += __shfl_xor_sync(0xffffffffu, sum1, 1);
        sum1 += __shfl_xor_sync(0xffffffffu, sum1, 2);
        float inv0 = 1.0f / sum0, inv1 = 1.0f / sum1;
        // store normalized P (tf32-rounded) to sS [128][132]
        #pragma unroll
        for (int ni = 0; ni < 16; ni++) {
            int c = ni * 8 + 2 * q4;
            *reinterpret_cast<float2*>(sm + OS + r0 * 132 + c) =
                make_float2(__uint_as_float(f2tf32(acc2[ni][0] * inv0)),
                            __uint_as_float(f2tf32(acc2[ni][1] * inv0)));
            *reinterpret_cast<float2*>(sm + OS + r1 * 132 + c) =
                make_float2(__uint_as_float(f2tf32(acc2[ni][2] * inv1)),
                            __uint_as_float(f2tf32(acc2[ni][3] * inv1)));
        }
    }
    __syncwarp();

    // ================= Phase 4: O = P V (single-pass tf32) =================
    float acc4[8][4];
    #pragma unroll
    for (int ni = 0; ni < 8; ni++)
        #pragma unroll
        for (int j = 0; j < 4; j++) acc4[ni][j] = 0.f;

    #pragma unroll
    for (int k8 = 0; k8 < 16; k8++) {
        int kk = k8 * 8 + q4;
        uint32_t ap[4];
        ap[0] = __float_as_uint(sm[OS + (m0 + g) * 132 + kk]);
        ap[1] = __float_as_uint(sm[OS + (m0 + g + 8) * 132 + kk]);
        ap[2] = __float_as_uint(sm[OS + (m0 + g) * 132 + kk + 4]);
        ap[3] = __float_as_uint(sm[OS + (m0 + g + 8) * 132 + kk + 4]);
        #pragma unroll
        for (int ni = 0; ni < 8; ni++) {
            int voff = kk * 72 + ni * 8 + g;
            uint32_t b0 = __float_as_uint(sm[OV + voff]);
            uint32_t b1 = __float_as_uint(sm[OV + voff + 288]);
            mma_tf32(acc4[ni], ap, b0, b1);
        }
    }

    // ================= epilogue =================
    {
        float* ob = out + (size_t)b * TT * HD;
        #pragma unroll
        for (int ni = 0; ni < 8; ni++) {
            int c = ni * 8 + 2 * q4;
            *reinterpret_cast<float2*>(ob + (m0 + g) * HD + c) =
                make_float2(acc4[ni][0], acc4[ni][1]);
            *reinterpret_cast<float2*>(ob + (m0 + g + 8) * HD + c) =
                make_float2(acc4[ni][2], acc4[ni][3]);
        }
    }
}

extern "C" void kernel_launch(void* const* d_in, const int* in_sizes, int n_in,
                              void* d_out, int out_size) {
    const float* x  = (const float*)d_in[0];
    const float* Wq = (const float*)d_in[1];
    const float* Wk = (const float*)d_in[2];
    const float* Wv = (const float*)d_in[3];
    float* out = (float*)d_out;

    cudaFuncSetAttribute(head_mma_kernel,
                         cudaFuncAttributeMaxDynamicSharedMemorySize, SMEM_BYTES);
    head_mma_kernel<<<BB, NT, SMEM_BYTES>>>(x, Wq, Wk, Wv, out);
}